// round 2
// baseline (speedup 1.0000x reference)
#include <cuda_runtime.h>
#include <cuda_bf16.h>

#define DN 128
#define CN 86
#define NODE_TILE 64
#define EDGE_TILE 128
#define MAX_EDGES 1000000

// Per-node partials: P[n][0..127] = h[n] @ W1u + b1, P[n][128..255] = h[n] @ W1v
__device__ float g_P[100000 * 256];
__device__ int   g_src32[MAX_EDGES];
__device__ int   g_dst32[MAX_EDGES];
__device__ int   g_use64;   // 1 if inputs really are int64

// ---------------------------------------------------------------------------
// Index dtype sniffer: if src/dst are int32 but we read int64, values are two
// packed int32s (almost surely out of [0, n_nodes)). Check first 1024 "int64"
// values; all in range -> int64, else int32.
// ---------------------------------------------------------------------------
__global__ void sniff_kernel(const void* src, int n_edges, int n_nodes)
{
    __shared__ int bad;
    if (threadIdx.x == 0) bad = 0;
    __syncthreads();
    const long long* p = (const long long*)src;
    int n_check = n_edges < 1024 ? n_edges : 1024;
    for (int i = threadIdx.x; i < n_check; i += blockDim.x) {
        long long v = p[i];
        if (v < 0 || v >= (long long)n_nodes) atomicOr(&bad, 1);
    }
    __syncthreads();
    if (threadIdx.x == 0) g_use64 = bad ? 0 : 1;
}

__global__ void convert_kernel(const void* src, const void* dst, int n_edges)
{
    int i = blockIdx.x * blockDim.x + threadIdx.x;
    if (i >= n_edges) return;
    if (g_use64) {
        g_src32[i] = (int)((const long long*)src)[i];
        g_dst32[i] = (int)((const long long*)dst)[i];
    } else {
        g_src32[i] = ((const int*)src)[i];
        g_dst32[i] = ((const int*)dst)[i];
    }
}

// ---------------------------------------------------------------------------
// Kernel A: node GEMM  P[n_nodes,256] = h @ [W1u | W1v], u-half gets +b1.
// Block 256 threads (16x16), tile 64 nodes x 256 cols.
// ---------------------------------------------------------------------------
__global__ void __launch_bounds__(256) node_gemm_kernel(
    const float* __restrict__ h, const float* __restrict__ W1,
    const float* __restrict__ b1, int n_nodes)
{
    extern __shared__ float sm[];
    float* As = sm;                  // [64][132]
    float* Bs = sm + 64 * 132;       // [16][256]

    const int n0 = blockIdx.x * NODE_TILE;
    const int tid = threadIdx.x;
    const int tx = tid & 15;
    const int ty = tid >> 4;

    #pragma unroll
    for (int i = tid; i < NODE_TILE * 32; i += 256) {
        int r = i >> 5, v = i & 31;
        float4 val = make_float4(0.f, 0.f, 0.f, 0.f);
        if (n0 + r < n_nodes)
            val = *reinterpret_cast<const float4*>(&h[(size_t)(n0 + r) * DN + 4 * v]);
        *reinterpret_cast<float4*>(&As[r * 132 + 4 * v]) = val;
    }

    float acc[4][16];
    #pragma unroll
    for (int j = 0; j < 4; j++)
        #pragma unroll
        for (int c = 0; c < 16; c++) acc[j][c] = 0.f;

    for (int kc = 0; kc < DN; kc += 16) {
        __syncthreads();
        #pragma unroll
        for (int i = tid; i < 16 * 64; i += 256) {
            int r = i >> 6, v = i & 63;
            int j = v * 4;
            const float* srcp = (j < DN) ? &W1[(size_t)(kc + r) * DN + j]
                                         : &W1[(size_t)(DN + kc + r) * DN + (j - DN)];
            *reinterpret_cast<float4*>(&Bs[r * 256 + j]) =
                *reinterpret_cast<const float4*>(srcp);
        }
        __syncthreads();

        #pragma unroll
        for (int k = 0; k < 16; k++) {
            float a[4], b[16];
            #pragma unroll
            for (int j = 0; j < 4; j++) a[j] = As[(ty * 4 + j) * 132 + kc + k];
            #pragma unroll
            for (int c = 0; c < 16; c++) b[c] = Bs[k * 256 + tx + 16 * c];
            #pragma unroll
            for (int j = 0; j < 4; j++)
                #pragma unroll
                for (int c = 0; c < 16; c++)
                    acc[j][c] = fmaf(a[j], b[c], acc[j][c]);
        }
    }

    #pragma unroll
    for (int j = 0; j < 4; j++) {
        int node = n0 + ty * 4 + j;
        if (node < n_nodes) {
            #pragma unroll
            for (int c = 0; c < 16; c++) {
                int col = tx + 16 * c;
                float v = acc[j][c];
                if (col < DN) v += b1[col];   // fold b1 into u-half
                g_P[(size_t)node * 256 + col] = v;
            }
        }
    }
}

// ---------------------------------------------------------------------------
// Kernel B: per-edge MLP: hid = relu(Pu[src] + Pv[dst]); out = hid@W2 + b2.
// Block 256 threads (16x16), tile 128 edges x 96 cols (86 padded).
// ---------------------------------------------------------------------------
__global__ void __launch_bounds__(256) edge_mlp_kernel(
    const float* __restrict__ W2, const float* __restrict__ b2,
    float* __restrict__ out, int n_edges)
{
    extern __shared__ float sm[];
    float* HID = sm;                       // [128][132]
    float* W2s = sm + EDGE_TILE * 132;     // [128][96]

    const int e0 = blockIdx.x * EDGE_TILE;
    const int tid = threadIdx.x;
    const int tx = tid & 15;
    const int ty = tid >> 4;

    #pragma unroll
    for (int i = tid; i < DN * 96; i += 256) {
        int r = i / 96, c = i % 96;
        W2s[i] = (c < CN) ? W2[r * CN + c] : 0.f;
    }

    // Gather + add + relu -> HID. Warp = one edge row (32 lanes x float4).
    #pragma unroll
    for (int i = tid; i < EDGE_TILE * 32; i += 256) {
        int e = i >> 5, v = i & 31;
        int eg = e0 + e;
        float4 hv = make_float4(0.f, 0.f, 0.f, 0.f);
        if (eg < n_edges) {
            int s = g_src32[eg];
            int d = g_dst32[eg];
            float4 u = *reinterpret_cast<const float4*>(&g_P[(size_t)s * 256 + 4 * v]);
            float4 w = *reinterpret_cast<const float4*>(&g_P[(size_t)d * 256 + 128 + 4 * v]);
            hv.x = fmaxf(u.x + w.x, 0.f);
            hv.y = fmaxf(u.y + w.y, 0.f);
            hv.z = fmaxf(u.z + w.z, 0.f);
            hv.w = fmaxf(u.w + w.w, 0.f);
        }
        *reinterpret_cast<float4*>(&HID[e * 132 + 4 * v]) = hv;
    }
    __syncthreads();

    float acc[8][6];
    #pragma unroll
    for (int j = 0; j < 8; j++)
        #pragma unroll
        for (int c = 0; c < 6; c++) acc[j][c] = 0.f;

    #pragma unroll 4
    for (int k = 0; k < DN; k++) {
        float a[8], b[6];
        #pragma unroll
        for (int j = 0; j < 8; j++) a[j] = HID[(ty * 8 + j) * 132 + k];
        #pragma unroll
        for (int c = 0; c < 6; c++) b[c] = W2s[k * 96 + tx + 16 * c];
        #pragma unroll
        for (int j = 0; j < 8; j++)
            #pragma unroll
            for (int c = 0; c < 6; c++)
                acc[j][c] = fmaf(a[j], b[c], acc[j][c]);
    }

    #pragma unroll
    for (int c = 0; c < 6; c++) {
        int col = tx + 16 * c;
        if (col >= CN) continue;
        float bias = b2[col];
        #pragma unroll
        for (int j = 0; j < 8; j++) {
            int eg = e0 + ty * 8 + j;
            if (eg < n_edges)
                out[(size_t)eg * CN + col] = acc[j][c] + bias;
        }
    }
}

extern "C" void kernel_launch(void* const* d_in, const int* in_sizes, int n_in,
                              void* d_out, int out_size)
{
    const float* h   = (const float*)d_in[0];
    const float* W1  = (const float*)d_in[1];
    const float* b1  = (const float*)d_in[2];
    const float* W2  = (const float*)d_in[3];
    const float* b2  = (const float*)d_in[4];
    const void*  src = d_in[5];
    const void*  dst = d_in[6];
    float* out = (float*)d_out;

    const int n_nodes = in_sizes[0] / DN;
    const int n_edges = in_sizes[5];

    sniff_kernel<<<1, 256>>>(src, n_edges, n_nodes);
    convert_kernel<<<(n_edges + 255) / 256, 256>>>(src, dst, n_edges);

    const int smemA = (64 * 132 + 16 * 256) * sizeof(float);       // 50176 B
    const int smemB = (EDGE_TILE * 132 + DN * 96) * sizeof(float); // 116736 B
    cudaFuncSetAttribute(node_gemm_kernel, cudaFuncAttributeMaxDynamicSharedMemorySize, smemA);
    cudaFuncSetAttribute(edge_mlp_kernel,  cudaFuncAttributeMaxDynamicSharedMemorySize, smemB);

    int gridA = (n_nodes + NODE_TILE - 1) / NODE_TILE;
    node_gemm_kernel<<<gridA, 256, smemA>>>(h, W1, b1, n_nodes);

    int gridB = (n_edges + EDGE_TILE - 1) / EDGE_TILE;
    edge_mlp_kernel<<<gridB, 256, smemB>>>(W2, b2, out, n_edges);
}

// round 4
// speedup vs baseline: 1.0185x; 1.0185x over previous
#include <cuda_runtime.h>
#include <cstdint>

#define DN 128
#define CN 86
#define NP 96
#define NODE_TILE 64
#define EDGE_TILE 128
#define MAX_EDGES 1000000
#define PITCH 132   // smem row pitch in floats: (132 mod 32)=4 -> conflict-free frags

__device__ float g_P[100000 * 256];   // [n][0:128]=h@W1u+b1, [n][128:256]=h@W1v
__device__ int   g_src32[MAX_EDGES];
__device__ int   g_dst32[MAX_EDGES];
__device__ int   g_use64;
__device__ float g_W2T[NP * DN];      // W2 transposed [n][k], tf32-rounded, rows 86..95 = 0

__device__ __forceinline__ uint32_t f2tf32(float f) {
    uint32_t u;
    asm("cvt.rna.tf32.f32 %0, %1;" : "=r"(u) : "f"(f));
    return u;
}

// m16n8k8 tf32 MMA, fp32 accumulate (baseline PTX, no 'a'-gate).
__device__ __forceinline__ void mma_tf32(float* c, const uint32_t* a, const uint32_t* b) {
    asm volatile(
        "mma.sync.aligned.m16n8k8.row.col.f32.tf32.tf32.f32 "
        "{%0,%1,%2,%3}, {%4,%5,%6,%7}, {%8,%9}, {%0,%1,%2,%3};"
        : "+f"(c[0]), "+f"(c[1]), "+f"(c[2]), "+f"(c[3])
        : "r"(a[0]), "r"(a[1]), "r"(a[2]), "r"(a[3]), "r"(b[0]), "r"(b[1]));
}

// ---------------------------------------------------------------------------
// Prep kernels
// ---------------------------------------------------------------------------
__global__ void sniff_kernel(const void* src, int n_edges, int n_nodes)
{
    __shared__ int bad;
    if (threadIdx.x == 0) bad = 0;
    __syncthreads();
    const long long* p = (const long long*)src;
    int n_check = n_edges < 1024 ? n_edges : 1024;
    for (int i = threadIdx.x; i < n_check; i += blockDim.x) {
        long long v = p[i];
        if (v < 0 || v >= (long long)n_nodes) atomicOr(&bad, 1);
    }
    __syncthreads();
    if (threadIdx.x == 0) g_use64 = bad ? 0 : 1;
}

__global__ void convert_kernel(const void* src, const void* dst, int n_edges)
{
    int i = blockIdx.x * blockDim.x + threadIdx.x;
    if (i >= n_edges) return;
    if (g_use64) {
        g_src32[i] = (int)((const long long*)src)[i];
        g_dst32[i] = (int)((const long long*)dst)[i];
    } else {
        g_src32[i] = ((const int*)src)[i];
        g_dst32[i] = ((const int*)dst)[i];
    }
}

__global__ void w2t_kernel(const float* __restrict__ W2)
{
    int i = blockIdx.x * blockDim.x + threadIdx.x;
    if (i >= NP * DN) return;
    int n = i >> 7, k = i & 127;
    float v = (n < CN) ? W2[k * CN + n] : 0.f;
    g_W2T[i] = __uint_as_float(f2tf32(v));
}

// ---------------------------------------------------------------------------
// Kernel A: node GEMM (fp32 FFMA) — unchanged from R2 (passing).
// ---------------------------------------------------------------------------
__global__ void __launch_bounds__(256) node_gemm_kernel(
    const float* __restrict__ h, const float* __restrict__ W1,
    const float* __restrict__ b1, int n_nodes)
{
    extern __shared__ float sm[];
    float* As = sm;                  // [64][132]
    float* Bs = sm + 64 * 132;       // [16][256]

    const int n0 = blockIdx.x * NODE_TILE;
    const int tid = threadIdx.x;
    const int tx = tid & 15;
    const int ty = tid >> 4;

    #pragma unroll
    for (int i = tid; i < NODE_TILE * 32; i += 256) {
        int r = i >> 5, v = i & 31;
        float4 val = make_float4(0.f, 0.f, 0.f, 0.f);
        if (n0 + r < n_nodes)
            val = *reinterpret_cast<const float4*>(&h[(size_t)(n0 + r) * DN + 4 * v]);
        *reinterpret_cast<float4*>(&As[r * 132 + 4 * v]) = val;
    }

    float acc[4][16];
    #pragma unroll
    for (int j = 0; j < 4; j++)
        #pragma unroll
        for (int c = 0; c < 16; c++) acc[j][c] = 0.f;

    for (int kc = 0; kc < DN; kc += 16) {
        __syncthreads();
        #pragma unroll
        for (int i = tid; i < 16 * 64; i += 256) {
            int r = i >> 6, v = i & 63;
            int j = v * 4;
            const float* srcp = (j < DN) ? &W1[(size_t)(kc + r) * DN + j]
                                         : &W1[(size_t)(DN + kc + r) * DN + (j - DN)];
            *reinterpret_cast<float4*>(&Bs[r * 256 + j]) =
                *reinterpret_cast<const float4*>(srcp);
        }
        __syncthreads();

        #pragma unroll
        for (int k = 0; k < 16; k++) {
            float a[4], b[16];
            #pragma unroll
            for (int j = 0; j < 4; j++) a[j] = As[(ty * 4 + j) * 132 + kc + k];
            #pragma unroll
            for (int c = 0; c < 16; c++) b[c] = Bs[k * 256 + tx + 16 * c];
            #pragma unroll
            for (int j = 0; j < 4; j++)
                #pragma unroll
                for (int c = 0; c < 16; c++)
                    acc[j][c] = fmaf(a[j], b[c], acc[j][c]);
        }
    }

    #pragma unroll
    for (int j = 0; j < 4; j++) {
        int node = n0 + ty * 4 + j;
        if (node < n_nodes) {
            #pragma unroll
            for (int c = 0; c < 16; c++) {
                int col = tx + 16 * c;
                float v = acc[j][c];
                if (col < DN) v += b1[col];
                g_P[(size_t)node * 256 + col] = v;
            }
        }
    }
}

// ---------------------------------------------------------------------------
// Kernel B: edge MLP on mma.sync tf32 (HMMA).
// 128 edges x 96 cols per CTA, K=128. 8 warps: 4 row-groups x 2 col-groups,
// each warp owns 32x48 = 2 m16-tiles x 6 n8-tiles.
// SMEM: HID [128][132] fp32(tf32 bits) + W2s [96][132] = 118272 B.
// ---------------------------------------------------------------------------
#define SMEM_EDGE_FLOATS ((EDGE_TILE + NP) * PITCH)

__global__ void __launch_bounds__(256) edge_mma_kernel(
    const float* __restrict__ b2, float* __restrict__ out, int n_edges)
{
    extern __shared__ float sm[];
    float* HID = sm;                      // [128][132]
    float* W2s = sm + EDGE_TILE * PITCH;  // [96][132]

    const int tid  = threadIdx.x;
    const int wid  = tid >> 5;
    const int lane = tid & 31;
    const int e0   = blockIdx.x * EDGE_TILE;

    const int wr = wid & 3;   // row group: 32 edges
    const int wc = wid >> 2;  // col group: 48 cols

    // Stage W2T (already tf32-rounded) -> [n][k] pitch 132.
    #pragma unroll
    for (int i = tid; i < NP * 32; i += 256) {
        int n = i >> 5, v = i & 31;
        float4 w = *reinterpret_cast<const float4*>(&g_W2T[n * DN + 4 * v]);
        *reinterpret_cast<float4*>(&W2s[n * PITCH + 4 * v]) = w;
    }

    // Gather + add + relu -> tf32 bits -> HID. Warp = one edge row per iter.
    #pragma unroll
    for (int i = tid; i < EDGE_TILE * 32; i += 256) {
        int e = i >> 5, v = i & 31;
        int eg = e0 + e;
        float4 hv = make_float4(0.f, 0.f, 0.f, 0.f);
        if (eg < n_edges) {
            int s = g_src32[eg];
            int d = g_dst32[eg];
            float4 u = *reinterpret_cast<const float4*>(&g_P[(size_t)s * 256 + 4 * v]);
            float4 w = *reinterpret_cast<const float4*>(&g_P[(size_t)d * 256 + 128 + 4 * v]);
            hv.x = __uint_as_float(f2tf32(fmaxf(u.x + w.x, 0.f)));
            hv.y = __uint_as_float(f2tf32(fmaxf(u.y + w.y, 0.f)));
            hv.z = __uint_as_float(f2tf32(fmaxf(u.z + w.z, 0.f)));
            hv.w = __uint_as_float(f2tf32(fmaxf(u.w + w.w, 0.f)));
        }
        *reinterpret_cast<float4*>(&HID[e * PITCH + 4 * v]) = hv;
    }
    __syncthreads();

    // MMA mainloop: 16 k-steps of 8.
    float c[12][4];
    #pragma unroll
    for (int t = 0; t < 12; t++)
        #pragma unroll
        for (int r = 0; r < 4; r++) c[t][r] = 0.f;

    const int arow = wr * 32 + (lane >> 2);
    const int bcol = wc * 48 + (lane >> 2);
    const int kq   = lane & 3;

    #pragma unroll
    for (int kk = 0; kk < 16; kk++) {
        const int k0 = kk * 8 + kq;
        uint32_t a[2][4];
        #pragma unroll
        for (int t = 0; t < 2; t++) {
            const float* p = &HID[(arow + t * 16) * PITCH + k0];
            a[t][0] = __float_as_uint(p[0]);
            a[t][1] = __float_as_uint(p[8 * PITCH]);
            a[t][2] = __float_as_uint(p[4]);
            a[t][3] = __float_as_uint(p[8 * PITCH + 4]);
        }
        uint32_t b[6][2];
        #pragma unroll
        for (int j = 0; j < 6; j++) {
            const float* p = &W2s[(bcol + j * 8) * PITCH + kk * 8 + kq];
            b[j][0] = __float_as_uint(p[0]);
            b[j][1] = __float_as_uint(p[4]);
        }
        #pragma unroll
        for (int t = 0; t < 2; t++)
            #pragma unroll
            for (int j = 0; j < 6; j++)
                mma_tf32(c[t * 6 + j], a[t], b[j]);
    }
    __syncthreads();

    // Epilogue 1: fragments -> smem staging [128][86] (reuse HID region).
    float* OUTS = HID;
    {
        const int row = wr * 32 + (lane >> 2);
        const int cb  = 2 * (lane & 3);
        #pragma unroll
        for (int t = 0; t < 2; t++) {
            #pragma unroll
            for (int j = 0; j < 6; j++) {
                int col = wc * 48 + j * 8 + cb;
                #pragma unroll
                for (int r = 0; r < 4; r++) {
                    int cc = col + (r & 1);
                    int rr = row + t * 16 + ((r >> 1) << 3);
                    if (cc < CN)
                        OUTS[rr * CN + cc] = c[t * 6 + j][r] + b2[cc];
                }
            }
        }
    }
    __syncthreads();

    // Epilogue 2: coalesced copy SMEM -> GMEM.
    int valid = n_edges - e0;
    if (valid > EDGE_TILE) valid = EDGE_TILE;
    int total = valid * CN;
    float* dstp = out + (size_t)e0 * CN;
    for (int i = tid; i < total; i += 256) dstp[i] = OUTS[i];
}

// ---------------------------------------------------------------------------
extern "C" void kernel_launch(void* const* d_in, const int* in_sizes, int n_in,
                              void* d_out, int out_size)
{
    const float* h   = (const float*)d_in[0];
    const float* W1  = (const float*)d_in[1];
    const float* b1  = (const float*)d_in[2];
    const float* W2  = (const float*)d_in[3];
    const float* b2  = (const float*)d_in[4];
    const void*  src = d_in[5];
    const void*  dst = d_in[6];
    float* out = (float*)d_out;

    const int n_nodes = in_sizes[0] / DN;
    const int n_edges = in_sizes[5];

    sniff_kernel<<<1, 256>>>(src, n_edges, n_nodes);
    convert_kernel<<<(n_edges + 255) / 256, 256>>>(src, dst, n_edges);
    w2t_kernel<<<(NP * DN + 255) / 256, 256>>>(W2);

    const int smemA = (64 * 132 + 16 * 256) * sizeof(float);
    const int smemB = SMEM_EDGE_FLOATS * sizeof(float);  // 118272
    cudaFuncSetAttribute(node_gemm_kernel, cudaFuncAttributeMaxDynamicSharedMemorySize, smemA);
    cudaFuncSetAttribute(edge_mma_kernel,  cudaFuncAttributeMaxDynamicSharedMemorySize, smemB);

    int gridA = (n_nodes + NODE_TILE - 1) / NODE_TILE;
    node_gemm_kernel<<<gridA, 256, smemA>>>(h, W1, b1, n_nodes);

    int gridB = (n_edges + EDGE_TILE - 1) / EDGE_TILE;
    edge_mma_kernel<<<gridB, 256, smemB>>>(b2, out, n_edges);
}

// round 6
// speedup vs baseline: 1.5103x; 1.4828x over previous
#include <cuda_runtime.h>
#include <cstdint>

#define DN 128
#define CN 86
#define NP 96
#define NODE_TILE 64
#define ETILE 64            // edges per pipeline tile
#define MAX_EDGES 1000000
#define PITCH 132

__device__ float g_P[100000 * 256];   // [n][0:128]=h@W1u+b1, [n][128:256]=h@W1v
__device__ int   g_src32[MAX_EDGES];
__device__ int   g_dst32[MAX_EDGES];
__device__ int   g_use64;
__device__ float g_W2T[NP * DN];      // W2^T [n][k], tf32-rounded, rows 86..95 = 0

// Shared-memory float offsets (persistent edge kernel)
#define OFF_W2   0                       // [96][132]   12672 floats
#define OFF_U0   12672                   // [64][132]    8448
#define OFF_U1   21120
#define OFF_V0   29568
#define OFF_V1   38016
#define SMEM_EDGE_FLOATS 46464           // 185856 bytes

__device__ __forceinline__ uint32_t f2tf32(float f) {
    uint32_t u;
    asm("cvt.rna.tf32.f32 %0, %1;" : "=r"(u) : "f"(f));
    return u;
}
__device__ __forceinline__ uint32_t smem_u32(const void* p) {
    uint32_t a;
    asm("{ .reg .u64 t; cvta.to.shared.u64 t, %1; cvt.u32.u64 %0, t; }"
        : "=r"(a) : "l"(p));
    return a;
}
__device__ __forceinline__ void cp16(uint32_t dst, const void* gsrc) {
    asm volatile("cp.async.cg.shared.global [%0], [%1], 16;"
                 :: "r"(dst), "l"(__cvta_generic_to_global(gsrc)) : "memory");
}
__device__ __forceinline__ void cp_commit() {
    asm volatile("cp.async.commit_group;" ::: "memory");
}
__device__ __forceinline__ void cp_wait1() {
    asm volatile("cp.async.wait_group 1;" ::: "memory");
}
__device__ __forceinline__ void mma_tf32(float* c, const uint32_t* a, const uint32_t* b) {
    asm volatile(
        "mma.sync.aligned.m16n8k8.row.col.f32.tf32.tf32.f32 "
        "{%0,%1,%2,%3}, {%4,%5,%6,%7}, {%8,%9}, {%0,%1,%2,%3};"
        : "+f"(c[0]), "+f"(c[1]), "+f"(c[2]), "+f"(c[3])
        : "r"(a[0]), "r"(a[1]), "r"(a[2]), "r"(a[3]), "r"(b[0]), "r"(b[1]));
}

// ---------------------------------------------------------------------------
// Prep kernels
// ---------------------------------------------------------------------------
__global__ void sniff_kernel(const void* src, int n_edges, int n_nodes)
{
    __shared__ int bad;
    if (threadIdx.x == 0) bad = 0;
    __syncthreads();
    const long long* p = (const long long*)src;
    int n_check = n_edges < 1024 ? n_edges : 1024;
    for (int i = threadIdx.x; i < n_check; i += blockDim.x) {
        long long v = p[i];
        if (v < 0 || v >= (long long)n_nodes) atomicOr(&bad, 1);
    }
    __syncthreads();
    if (threadIdx.x == 0) g_use64 = bad ? 0 : 1;
}

__global__ void convert_kernel(const void* src, const void* dst, int n_edges)
{
    int i = blockIdx.x * blockDim.x + threadIdx.x;
    if (i >= n_edges) return;
    if (g_use64) {
        g_src32[i] = (int)((const long long*)src)[i];
        g_dst32[i] = (int)((const long long*)dst)[i];
    } else {
        g_src32[i] = ((const int*)src)[i];
        g_dst32[i] = ((const int*)dst)[i];
    }
}

__global__ void w2t_kernel(const float* __restrict__ W2)
{
    int i = blockIdx.x * blockDim.x + threadIdx.x;
    if (i >= NP * DN) return;
    int n = i >> 7, k = i & 127;
    float v = (n < CN) ? W2[k * CN + n] : 0.f;
    g_W2T[i] = __uint_as_float(f2tf32(v));
}

// ---------------------------------------------------------------------------
// Kernel A: node GEMM (fp32 FFMA) — unchanged (305us, later target).
// ---------------------------------------------------------------------------
__global__ void __launch_bounds__(256) node_gemm_kernel(
    const float* __restrict__ h, const float* __restrict__ W1,
    const float* __restrict__ b1, int n_nodes)
{
    extern __shared__ float sm[];
    float* As = sm;
    float* Bs = sm + 64 * 132;

    const int n0 = blockIdx.x * NODE_TILE;
    const int tid = threadIdx.x;
    const int tx = tid & 15;
    const int ty = tid >> 4;

    #pragma unroll
    for (int i = tid; i < NODE_TILE * 32; i += 256) {
        int r = i >> 5, v = i & 31;
        float4 val = make_float4(0.f, 0.f, 0.f, 0.f);
        if (n0 + r < n_nodes)
            val = *reinterpret_cast<const float4*>(&h[(size_t)(n0 + r) * DN + 4 * v]);
        *reinterpret_cast<float4*>(&As[r * 132 + 4 * v]) = val;
    }

    float acc[4][16];
    #pragma unroll
    for (int j = 0; j < 4; j++)
        #pragma unroll
        for (int c = 0; c < 16; c++) acc[j][c] = 0.f;

    for (int kc = 0; kc < DN; kc += 16) {
        __syncthreads();
        #pragma unroll
        for (int i = tid; i < 16 * 64; i += 256) {
            int r = i >> 6, v = i & 63;
            int j = v * 4;
            const float* srcp = (j < DN) ? &W1[(size_t)(kc + r) * DN + j]
                                         : &W1[(size_t)(DN + kc + r) * DN + (j - DN)];
            *reinterpret_cast<float4*>(&Bs[r * 256 + j]) =
                *reinterpret_cast<const float4*>(srcp);
        }
        __syncthreads();

        #pragma unroll
        for (int k = 0; k < 16; k++) {
            float a[4], b[16];
            #pragma unroll
            for (int j = 0; j < 4; j++) a[j] = As[(ty * 4 + j) * 132 + kc + k];
            #pragma unroll
            for (int c = 0; c < 16; c++) b[c] = Bs[k * 256 + tx + 16 * c];
            #pragma unroll
            for (int j = 0; j < 4; j++)
                #pragma unroll
                for (int c = 0; c < 16; c++)
                    acc[j][c] = fmaf(a[j], b[c], acc[j][c]);
        }
    }

    #pragma unroll
    for (int j = 0; j < 4; j++) {
        int node = n0 + ty * 4 + j;
        if (node < n_nodes) {
            #pragma unroll
            for (int c = 0; c < 16; c++) {
                int col = tx + 16 * c;
                float v = acc[j][c];
                if (col < DN) v += b1[col];
                g_P[(size_t)node * 256 + col] = v;
            }
        }
    }
}

// ---------------------------------------------------------------------------
// Kernel B: persistent pipelined edge MLP (cp.async gather + HMMA tf32).
// Tile = 64 edges. U/V double-buffered; W2 staged once.
// 8 warps: wr=wid&1 (32 rows), wc=wid>>1 (24 cols = 3 n8-tiles).
// ---------------------------------------------------------------------------
__global__ void __launch_bounds__(256) edge_mma_kernel(
    const float* __restrict__ b2, float* __restrict__ out,
    int n_edges, int n_tiles)
{
    extern __shared__ float sm[];
    float* W2s = sm + OFF_W2;
    float* Ubuf[2] = { sm + OFF_U0, sm + OFF_U1 };
    float* Vbuf[2] = { sm + OFF_V0, sm + OFF_V1 };

    const int tid  = threadIdx.x;
    const int wid  = tid >> 5;
    const int lane = tid & 31;
    const int G    = gridDim.x;

    const uint32_t u_s32[2] = { smem_u32(Ubuf[0]), smem_u32(Ubuf[1]) };
    const uint32_t v_s32[2] = { smem_u32(Vbuf[0]), smem_u32(Vbuf[1]) };

    // Stage W2 once.
    #pragma unroll
    for (int i = tid; i < NP * 32; i += 256) {
        int n = i >> 5, v = i & 31;
        float4 w = *reinterpret_cast<const float4*>(&g_W2T[n * DN + 4 * v]);
        *reinterpret_cast<float4*>(&W2s[n * PITCH + 4 * v]) = w;
    }

    const int e_loc = tid >> 2;          // 0..63
    const int q     = tid & 3;           // quarter of 128 floats

    auto prefetch = [&](int t, int stg) {
        if (t < n_tiles) {
            int eg = t * ETILE + e_loc;
            int s = 0, d = 0;
            if (eg < n_edges) { s = __ldg(&g_src32[eg]); d = __ldg(&g_dst32[eg]); }
            const float* usrc = &g_P[(size_t)s * 256 + q * 32];
            const float* vsrc = &g_P[(size_t)d * 256 + 128 + q * 32];
            uint32_t udst = u_s32[stg] + (e_loc * PITCH + q * 32) * 4;
            uint32_t vdst = v_s32[stg] + (e_loc * PITCH + q * 32) * 4;
            #pragma unroll
            for (int c2 = 0; c2 < 8; c2++) {
                cp16(udst + c2 * 16, usrc + c2 * 4);
                cp16(vdst + c2 * 16, vsrc + c2 * 4);
            }
        }
        cp_commit();   // commit (possibly empty) group to keep counts aligned
    };

    const int wr = wid & 1;
    const int wc = wid >> 1;
    const int arow = wr * 32 + (lane >> 2);
    const int bcol = wc * 24 + (lane >> 2);
    const int kq   = lane & 3;

    int stage = 0;
    prefetch(blockIdx.x, 0);

    for (int t = blockIdx.x; t < n_tiles; t += G) {
        prefetch(t + G, stage ^ 1);
        cp_wait1();              // tile t resident
        __syncthreads();

        // relu-add in place: U = tf32(relu(U+V))
        {
            float* up = &Ubuf[stage][e_loc * PITCH + q * 32];
            const float* vp = &Vbuf[stage][e_loc * PITCH + q * 32];
            #pragma unroll
            for (int c2 = 0; c2 < 8; c2++) {
                float4 u = *reinterpret_cast<const float4*>(up + 4 * c2);
                float4 v = *reinterpret_cast<const float4*>(vp + 4 * c2);
                u.x = __uint_as_float(f2tf32(fmaxf(u.x + v.x, 0.f)));
                u.y = __uint_as_float(f2tf32(fmaxf(u.y + v.y, 0.f)));
                u.z = __uint_as_float(f2tf32(fmaxf(u.z + v.z, 0.f)));
                u.w = __uint_as_float(f2tf32(fmaxf(u.w + v.w, 0.f)));
                *reinterpret_cast<float4*>(up + 4 * c2) = u;
            }
        }
        __syncthreads();

        // MMA 64x96x128: per warp 2 m16-tiles x 3 n8-tiles.
        float c[6][4];
        #pragma unroll
        for (int i = 0; i < 6; i++)
            #pragma unroll
            for (int r = 0; r < 4; r++) c[i][r] = 0.f;

        const float* Ub = Ubuf[stage];
        #pragma unroll
        for (int kk = 0; kk < 16; kk++) {
            const int k0 = kk * 8 + kq;
            uint32_t a[2][4];
            #pragma unroll
            for (int t2 = 0; t2 < 2; t2++) {
                const float* p = &Ub[(arow + t2 * 16) * PITCH + k0];
                a[t2][0] = __float_as_uint(p[0]);
                a[t2][1] = __float_as_uint(p[8 * PITCH]);
                a[t2][2] = __float_as_uint(p[4]);
                a[t2][3] = __float_as_uint(p[8 * PITCH + 4]);
            }
            uint32_t b[3][2];
            #pragma unroll
            for (int j = 0; j < 3; j++) {
                const float* p = &W2s[(bcol + j * 8) * PITCH + k0];
                b[j][0] = __float_as_uint(p[0]);
                b[j][1] = __float_as_uint(p[4]);
            }
            #pragma unroll
            for (int t2 = 0; t2 < 2; t2++)
                #pragma unroll
                for (int j = 0; j < 3; j++)
                    mma_tf32(c[t2 * 3 + j], a[t2], b[j]);
        }
        __syncthreads();   // V[stage] free for staging after this

        // Epilogue: fragments -> V[stage] as [64][86], then coalesced store.
        float* OUTS = Vbuf[stage];
        {
            const int row = wr * 32 + (lane >> 2);
            const int cb  = 2 * (lane & 3);
            #pragma unroll
            for (int t2 = 0; t2 < 2; t2++) {
                #pragma unroll
                for (int j = 0; j < 3; j++) {
                    int col = wc * 24 + j * 8 + cb;
                    #pragma unroll
                    for (int r = 0; r < 4; r++) {
                        int cc = col + (r & 1);
                        int rr = row + t2 * 16 + ((r >> 1) << 3);
                        if (cc < CN)
                            OUTS[rr * CN + cc] = c[t2 * 3 + j][r] + b2[cc];
                    }
                }
            }
        }
        __syncthreads();

        int e0 = t * ETILE;
        int valid = n_edges - e0;
        if (valid > ETILE) valid = ETILE;
        float* dstp = out + (size_t)e0 * CN;
        if (valid == ETILE) {
            const float4* s4 = reinterpret_cast<const float4*>(OUTS);
            float4* d4 = reinterpret_cast<float4*>(dstp);
            #pragma unroll
            for (int i = tid; i < ETILE * CN / 4; i += 256) d4[i] = s4[i];
        } else {
            for (int i = tid; i < valid * CN; i += 256) dstp[i] = OUTS[i];
        }
        __syncthreads();
        stage ^= 1;
    }
}

// ---------------------------------------------------------------------------
extern "C" void kernel_launch(void* const* d_in, const int* in_sizes, int n_in,
                              void* d_out, int out_size)
{
    const float* h   = (const float*)d_in[0];
    const float* W1  = (const float*)d_in[1];
    const float* b1  = (const float*)d_in[2];
    const float* W2  = (const float*)d_in[3];
    const float* b2  = (const float*)d_in[4];
    const void*  src = d_in[5];
    const void*  dst = d_in[6];
    float* out = (float*)d_out;

    const int n_nodes = in_sizes[0] / DN;
    const int n_edges = in_sizes[5];

    static int n_sm = 0;
    if (n_sm == 0) {
        cudaDeviceGetAttribute(&n_sm, cudaDevAttrMultiProcessorCount, 0);
        if (n_sm <= 0) n_sm = 148;
    }

    sniff_kernel<<<1, 256>>>(src, n_edges, n_nodes);
    convert_kernel<<<(n_edges + 255) / 256, 256>>>(src, dst, n_edges);
    w2t_kernel<<<(NP * DN + 255) / 256, 256>>>(W2);

    const int smemA = (64 * 132 + 16 * 256) * sizeof(float);
    const int smemB = SMEM_EDGE_FLOATS * sizeof(float);   // 185856
    cudaFuncSetAttribute(node_gemm_kernel, cudaFuncAttributeMaxDynamicSharedMemorySize, smemA);
    cudaFuncSetAttribute(edge_mma_kernel,  cudaFuncAttributeMaxDynamicSharedMemorySize, smemB);

    int gridA = (n_nodes + NODE_TILE - 1) / NODE_TILE;
    node_gemm_kernel<<<gridA, 256, smemA>>>(h, W1, b1, n_nodes);

    int n_tiles = (n_edges + ETILE - 1) / ETILE;
    edge_mma_kernel<<<n_sm, 256, smemB>>>(b2, out, n_edges, n_tiles);
}

// round 7
// speedup vs baseline: 1.5533x; 1.0285x over previous
#include <cuda_runtime.h>
#include <cstdint>

#define DN 128
#define CN 86
#define NP 96
#define NODE_TILE 64
#define ETILE 64            // edges per pipeline tile
#define MAX_EDGES 1000000
#define PITCH 132

__device__ float g_P[100000 * 256];   // [n][0:128]=h@W1u+b1, [n][128:256]=h@W1v
__device__ int   g_src32[MAX_EDGES];
__device__ int   g_dst32[MAX_EDGES];
__device__ int   g_use64;
__device__ float g_W2T[NP * DN];      // W2^T [n][k], tf32-rounded, rows 86..95 = 0

// Shared-memory float offsets (persistent edge kernel)
#define OFF_W2   0                       // [96][132]   12672 floats
#define OFF_U0   12672                   // [64][132]    8448
#define OFF_U1   21120
#define OFF_V0   29568
#define OFF_V1   38016
#define SMEM_EDGE_FLOATS 46464           // 185856 bytes

__device__ __forceinline__ uint32_t f2tf32(float f) {
    uint32_t u;
    asm("cvt.rna.tf32.f32 %0, %1;" : "=r"(u) : "f"(f));
    return u;
}
__device__ __forceinline__ uint32_t smem_u32(const void* p) {
    uint32_t a;
    asm("{ .reg .u64 t; cvta.to.shared.u64 t, %1; cvt.u32.u64 %0, t; }"
        : "=r"(a) : "l"(p));
    return a;
}
__device__ __forceinline__ void cp16(uint32_t dst, const void* gsrc) {
    asm volatile("cp.async.cg.shared.global [%0], [%1], 16;"
                 :: "r"(dst), "l"(__cvta_generic_to_global(gsrc)) : "memory");
}
__device__ __forceinline__ void cp_commit() {
    asm volatile("cp.async.commit_group;" ::: "memory");
}
__device__ __forceinline__ void cp_wait1() {
    asm volatile("cp.async.wait_group 1;" ::: "memory");
}
__device__ __forceinline__ void mma_tf32(float* c, const uint32_t* a, const uint32_t* b) {
    asm volatile(
        "mma.sync.aligned.m16n8k8.row.col.f32.tf32.tf32.f32 "
        "{%0,%1,%2,%3}, {%4,%5,%6,%7}, {%8,%9}, {%0,%1,%2,%3};"
        : "+f"(c[0]), "+f"(c[1]), "+f"(c[2]), "+f"(c[3])
        : "r"(a[0]), "r"(a[1]), "r"(a[2]), "r"(a[3]), "r"(b[0]), "r"(b[1]));
}

// ---------------------------------------------------------------------------
// Prep kernels
// ---------------------------------------------------------------------------
__global__ void sniff_kernel(const void* src, int n_edges, int n_nodes)
{
    __shared__ int bad;
    if (threadIdx.x == 0) bad = 0;
    __syncthreads();
    const long long* p = (const long long*)src;
    int n_check = n_edges < 1024 ? n_edges : 1024;
    for (int i = threadIdx.x; i < n_check; i += blockDim.x) {
        long long v = p[i];
        if (v < 0 || v >= (long long)n_nodes) atomicOr(&bad, 1);
    }
    __syncthreads();
    if (threadIdx.x == 0) g_use64 = bad ? 0 : 1;
}

__global__ void convert_kernel(const void* src, const void* dst, int n_edges)
{
    int i = blockIdx.x * blockDim.x + threadIdx.x;
    if (i >= n_edges) return;
    if (g_use64) {
        g_src32[i] = (int)((const long long*)src)[i];
        g_dst32[i] = (int)((const long long*)dst)[i];
    } else {
        g_src32[i] = ((const int*)src)[i];
        g_dst32[i] = ((const int*)dst)[i];
    }
}

__global__ void w2t_kernel(const float* __restrict__ W2)
{
    int i = blockIdx.x * blockDim.x + threadIdx.x;
    if (i >= NP * DN) return;
    int n = i >> 7, k = i & 127;
    float v = (n < CN) ? W2[k * CN + n] : 0.f;
    g_W2T[i] = __uint_as_float(f2tf32(v));
}

// ---------------------------------------------------------------------------
// Kernel A: node GEMM (fp32 FFMA) — unchanged (189us, later target).
// ---------------------------------------------------------------------------
__global__ void __launch_bounds__(256) node_gemm_kernel(
    const float* __restrict__ h, const float* __restrict__ W1,
    const float* __restrict__ b1, int n_nodes)
{
    extern __shared__ float sm[];
    float* As = sm;
    float* Bs = sm + 64 * 132;

    const int n0 = blockIdx.x * NODE_TILE;
    const int tid = threadIdx.x;
    const int tx = tid & 15;
    const int ty = tid >> 4;

    #pragma unroll
    for (int i = tid; i < NODE_TILE * 32; i += 256) {
        int r = i >> 5, v = i & 31;
        float4 val = make_float4(0.f, 0.f, 0.f, 0.f);
        if (n0 + r < n_nodes)
            val = *reinterpret_cast<const float4*>(&h[(size_t)(n0 + r) * DN + 4 * v]);
        *reinterpret_cast<float4*>(&As[r * 132 + 4 * v]) = val;
    }

    float acc[4][16];
    #pragma unroll
    for (int j = 0; j < 4; j++)
        #pragma unroll
        for (int c = 0; c < 16; c++) acc[j][c] = 0.f;

    for (int kc = 0; kc < DN; kc += 16) {
        __syncthreads();
        #pragma unroll
        for (int i = tid; i < 16 * 64; i += 256) {
            int r = i >> 6, v = i & 63;
            int j = v * 4;
            const float* srcp = (j < DN) ? &W1[(size_t)(kc + r) * DN + j]
                                         : &W1[(size_t)(DN + kc + r) * DN + (j - DN)];
            *reinterpret_cast<float4*>(&Bs[r * 256 + j]) =
                *reinterpret_cast<const float4*>(srcp);
        }
        __syncthreads();

        #pragma unroll
        for (int k = 0; k < 16; k++) {
            float a[4], b[16];
            #pragma unroll
            for (int j = 0; j < 4; j++) a[j] = As[(ty * 4 + j) * 132 + kc + k];
            #pragma unroll
            for (int c = 0; c < 16; c++) b[c] = Bs[k * 256 + tx + 16 * c];
            #pragma unroll
            for (int j = 0; j < 4; j++)
                #pragma unroll
                for (int c = 0; c < 16; c++)
                    acc[j][c] = fmaf(a[j], b[c], acc[j][c]);
        }
    }

    #pragma unroll
    for (int j = 0; j < 4; j++) {
        int node = n0 + ty * 4 + j;
        if (node < n_nodes) {
            #pragma unroll
            for (int c = 0; c < 16; c++) {
                int col = tx + 16 * c;
                float v = acc[j][c];
                if (col < DN) v += b1[col];
                g_P[(size_t)node * 256 + col] = v;
            }
        }
    }
}

// ---------------------------------------------------------------------------
// Kernel B: persistent pipelined edge MLP — now 512 threads / 16 warps.
// Tile = 64 edges. 16 warps: wr=wid&3 (16 rows, 1 m16 tile),
// wc=wid>>2 (24 cols = 3 n8-tiles).
// ---------------------------------------------------------------------------
#define ETHREADS 512

__global__ void __launch_bounds__(ETHREADS) edge_mma_kernel(
    const float* __restrict__ b2, float* __restrict__ out,
    int n_edges, int n_tiles)
{
    extern __shared__ float sm[];
    float* W2s = sm + OFF_W2;
    float* Ubuf[2] = { sm + OFF_U0, sm + OFF_U1 };
    float* Vbuf[2] = { sm + OFF_V0, sm + OFF_V1 };

    const int tid  = threadIdx.x;
    const int wid  = tid >> 5;
    const int lane = tid & 31;
    const int G    = gridDim.x;

    const uint32_t u_s32[2] = { smem_u32(Ubuf[0]), smem_u32(Ubuf[1]) };
    const uint32_t v_s32[2] = { smem_u32(Vbuf[0]), smem_u32(Vbuf[1]) };

    // Stage W2 once.
    #pragma unroll
    for (int i = tid; i < NP * 32; i += ETHREADS) {
        int n = i >> 5, v = i & 31;
        float4 w = *reinterpret_cast<const float4*>(&g_W2T[n * DN + 4 * v]);
        *reinterpret_cast<float4*>(&W2s[n * PITCH + 4 * v]) = w;
    }

    const int e_loc = tid >> 3;          // 0..63
    const int q     = tid & 7;           // eighth of 128 floats (16 floats)

    auto prefetch = [&](int t, int stg) {
        if (t < n_tiles) {
            int eg = t * ETILE + e_loc;
            int s = 0, d = 0;
            if (eg < n_edges) { s = __ldg(&g_src32[eg]); d = __ldg(&g_dst32[eg]); }
            const float* usrc = &g_P[(size_t)s * 256 + q * 16];
            const float* vsrc = &g_P[(size_t)d * 256 + 128 + q * 16];
            uint32_t udst = u_s32[stg] + (e_loc * PITCH + q * 16) * 4;
            uint32_t vdst = v_s32[stg] + (e_loc * PITCH + q * 16) * 4;
            #pragma unroll
            for (int c2 = 0; c2 < 4; c2++) {
                cp16(udst + c2 * 16, usrc + c2 * 4);
                cp16(vdst + c2 * 16, vsrc + c2 * 4);
            }
        }
        cp_commit();
    };

    const int wr = wid & 3;        // row group (16 edges)
    const int wc = wid >> 2;       // col group (24 cols)
    const int arow = wr * 16 + (lane >> 2);
    const int bcol = wc * 24 + (lane >> 2);
    const int kq   = lane & 3;

    int stage = 0;
    prefetch(blockIdx.x, 0);

    for (int t = blockIdx.x; t < n_tiles; t += G) {
        prefetch(t + G, stage ^ 1);
        cp_wait1();              // tile t resident
        __syncthreads();

        // relu-add in place: U = tf32(relu(U+V)); thread covers 16 floats.
        {
            float* up = &Ubuf[stage][e_loc * PITCH + q * 16];
            const float* vp = &Vbuf[stage][e_loc * PITCH + q * 16];
            #pragma unroll
            for (int c2 = 0; c2 < 4; c2++) {
                float4 u = *reinterpret_cast<const float4*>(up + 4 * c2);
                float4 v = *reinterpret_cast<const float4*>(vp + 4 * c2);
                u.x = __uint_as_float(f2tf32(fmaxf(u.x + v.x, 0.f)));
                u.y = __uint_as_float(f2tf32(fmaxf(u.y + v.y, 0.f)));
                u.z = __uint_as_float(f2tf32(fmaxf(u.z + v.z, 0.f)));
                u.w = __uint_as_float(f2tf32(fmaxf(u.w + v.w, 0.f)));
                *reinterpret_cast<float4*>(up + 4 * c2) = u;
            }
        }
        __syncthreads();

        // MMA 64x96x128: per warp 1 m16-tile x 3 n8-tiles.
        float c[3][4];
        #pragma unroll
        for (int i = 0; i < 3; i++)
            #pragma unroll
            for (int r = 0; r < 4; r++) c[i][r] = 0.f;

        const float* Ub = Ubuf[stage];
        #pragma unroll
        for (int kk = 0; kk < 16; kk++) {
            const int k0 = kk * 8 + kq;
            uint32_t a[4];
            {
                const float* p = &Ub[arow * PITCH + k0];
                a[0] = __float_as_uint(p[0]);
                a[1] = __float_as_uint(p[8 * PITCH]);
                a[2] = __float_as_uint(p[4]);
                a[3] = __float_as_uint(p[8 * PITCH + 4]);
            }
            uint32_t b[3][2];
            #pragma unroll
            for (int j = 0; j < 3; j++) {
                const float* p = &W2s[(bcol + j * 8) * PITCH + k0];
                b[j][0] = __float_as_uint(p[0]);
                b[j][1] = __float_as_uint(p[4]);
            }
            #pragma unroll
            for (int j = 0; j < 3; j++)
                mma_tf32(c[j], a, b[j]);
        }
        __syncthreads();   // V[stage] free for staging after this

        // Epilogue: fragments -> V[stage] as [64][86], then coalesced store.
        float* OUTS = Vbuf[stage];
        {
            const int row = wr * 16 + (lane >> 2);
            const int cb  = 2 * (lane & 3);
            #pragma unroll
            for (int j = 0; j < 3; j++) {
                int col = wc * 24 + j * 8 + cb;
                #pragma unroll
                for (int r = 0; r < 4; r++) {
                    int cc = col + (r & 1);
                    int rr = row + ((r >> 1) << 3);
                    if (cc < CN)
                        OUTS[rr * CN + cc] = c[j][r] + b2[cc];
                }
            }
        }
        __syncthreads();

        int e0 = t * ETILE;
        int valid = n_edges - e0;
        if (valid > ETILE) valid = ETILE;
        float* dstp = out + (size_t)e0 * CN;
        if (valid == ETILE) {
            const float4* s4 = reinterpret_cast<const float4*>(OUTS);
            float4* d4 = reinterpret_cast<float4*>(dstp);
            #pragma unroll
            for (int i = tid; i < ETILE * CN / 4; i += ETHREADS) d4[i] = s4[i];
        } else {
            for (int i = tid; i < valid * CN; i += ETHREADS) dstp[i] = OUTS[i];
        }
        __syncthreads();
        stage ^= 1;
    }
}

// ---------------------------------------------------------------------------
extern "C" void kernel_launch(void* const* d_in, const int* in_sizes, int n_in,
                              void* d_out, int out_size)
{
    const float* h   = (const float*)d_in[0];
    const float* W1  = (const float*)d_in[1];
    const float* b1  = (const float*)d_in[2];
    const float* W2  = (const float*)d_in[3];
    const float* b2  = (const float*)d_in[4];
    const void*  src = d_in[5];
    const void*  dst = d_in[6];
    float* out = (float*)d_out;

    const int n_nodes = in_sizes[0] / DN;
    const int n_edges = in_sizes[5];

    static int n_sm = 0;
    if (n_sm == 0) {
        cudaDeviceGetAttribute(&n_sm, cudaDevAttrMultiProcessorCount, 0);
        if (n_sm <= 0) n_sm = 148;
    }

    sniff_kernel<<<1, 256>>>(src, n_edges, n_nodes);
    convert_kernel<<<(n_edges + 255) / 256, 256>>>(src, dst, n_edges);
    w2t_kernel<<<(NP * DN + 255) / 256, 256>>>(W2);

    const int smemA = (64 * 132 + 16 * 256) * sizeof(float);
    const int smemB = SMEM_EDGE_FLOATS * sizeof(float);   // 185856
    cudaFuncSetAttribute(node_gemm_kernel, cudaFuncAttributeMaxDynamicSharedMemorySize, smemA);
    cudaFuncSetAttribute(edge_mma_kernel,  cudaFuncAttributeMaxDynamicSharedMemorySize, smemB);

    int gridA = (n_nodes + NODE_TILE - 1) / NODE_TILE;
    node_gemm_kernel<<<gridA, 256, smemA>>>(h, W1, b1, n_nodes);

    int n_tiles = (n_edges + ETILE - 1) / ETILE;
    edge_mma_kernel<<<n_sm, ETHREADS, smemB>>>(b2, out, n_edges, n_tiles);
}